// round 8
// baseline (speedup 1.0000x reference)
#include <cuda_runtime.h>
#include <math.h>
#include <stdint.h>

#define NTOK 32768
#define NE   64
#define NKTOP 8

// ===========================================================================
// scratch (device globals: allocation-free)
// ===========================================================================
__device__ __align__(16) float g_h1[(size_t)NTOK * 2048];
__device__ __align__(16) float g_h2[(size_t)NTOK * 2048];
__device__ __align__(16) float g_h4[(size_t)NTOK * 1024];
__device__ __align__(16) float g_logits [(size_t)NTOK * NE];
__device__ __align__(16) float g_nlogits[(size_t)NTOK * NE];

// ===========================================================================
// tf32 split-MMA GEMM: C[N,M] = relu(A[N,K] @ W[K,M] + bias)
// - mma.sync.m16n8k8 tf32 (base ISA, compiles for plain sm_103 target)
// - fp32 accuracy via 2-way tf32 split, 3 products (hh, hl, lh), err ~2^-22
// - R7: fragment-ordered smem. A stored as [T16][k8][lane][4], B as
//   [N8][k8][lane][2] so each mma fragment is ONE LDS.128 / LDS.64
//   (12 LDS/warp-k8 vs 32). Double-buffered (48KB/buf), 2 CTA/SM.
// - CTA 128x64, 8 warps x (32x32) warp tiles.
// ===========================================================================
#define A_HALF 4096                       // floats: 8 T-tiles x 4 k8 x 32 lanes x 4
#define B_HALF 2048                       // floats: 8 N-tiles x 4 k8 x 32 lanes x 2
#define BUF_FLOATS (2 * A_HALF + 2 * B_HALF)   // Ah|Al|Bh|Bl = 12288
#define SMEM_BYTES (2 * BUF_FLOATS * 4)        // 98,304 B

__device__ __forceinline__ float tf32r(float x) {
    uint32_t h;
    asm("cvt.rna.tf32.f32 %0, %1;" : "=r"(h) : "f"(x));
    return __uint_as_float(h);
}

__device__ __forceinline__ void mma8(float* c, const uint32_t* a, const uint32_t* b) {
    asm volatile(
        "mma.sync.aligned.m16n8k8.row.col.f32.tf32.tf32.f32 "
        "{%0,%1,%2,%3}, {%4,%5,%6,%7}, {%8,%9}, {%0,%1,%2,%3};"
        : "+f"(c[0]), "+f"(c[1]), "+f"(c[2]), "+f"(c[3])
        : "r"(a[0]), "r"(a[1]), "r"(a[2]), "r"(a[3]), "r"(b[0]), "r"(b[1]));
}

__global__ __launch_bounds__(256, 2)
void mm_tf32(const float* __restrict__ A, const float* __restrict__ B,
             const float* __restrict__ bias, float* __restrict__ C,
             int K, int M)
{
    extern __shared__ __align__(16) float sm[];

    const int tid  = threadIdx.x;
    const int lane = tid & 31;
    const int wid  = tid >> 5;
    const int row0 = blockIdx.y << 7;   // 128 rows / CTA
    const int col0 = blockIdx.x << 6;   // 64 cols / CTA
    const int wm   = (wid & 3) << 5;    // warp m-offset: 0/32/64/96
    const int wn   = (wid >> 2) << 5;   // warp n-offset: 0/32
    const int g    = lane >> 2;
    const int tig  = lane & 3;
    const int Tw   = (wid & 3) << 1;    // A tile16 base for this warp (+mt)
    const int NTw  = (wid >> 2) << 2;   // B tile8 base for this warp (+nt)

    // ---- global-load mapping: A 128x32 (4 f4/thr), B 32x64 (2 f4/thr) ----
    const int arow = tid >> 3;            // + 32*i
    const int aj   = (tid & 7) << 2;      // k-offset (mult of 4)
    const int brow = tid >> 4;            // + 16*i
    const int bj   = (tid & 15) << 2;     // n-offset (mult of 4)

    // ---- fragment-order store indices (precomputed) ----
    // A element (row, k): T=row>>4, g'=row&7, half=(row>>3)&1;
    //   k8=k>>3, tig'=k&3, khalf=(k>>2)&1; reg = half + 2*khalf
    //   idx = ((T*4+k8)*32 + g'*4+tig')*4 + reg
    const int k8a   = aj >> 3;
    const int aregb = (aj >> 2) & 1;      // khalf (half added per-row below)
    int aidx[4];
#pragma unroll
    for (int i = 0; i < 4; ++i) {
        const int row = arow + 32 * i;
        const int T   = row >> 4;
        const int gp  = row & 7;
        const int hf  = (row >> 3) & 1;
        aidx[i] = ((T * 4 + k8a) * 32 + gp * 4) * 4 + hf + 2 * aregb;  // + 4*t3
    }
    // B element (k, n): NT=n>>3, g'=n&7; k8=k>>3, tig'=k&3, reg=(k>>2)&1
    //   idx = ((NT*4+k8)*32 + g'*4+tig')*2 + reg
    const int bNT = bj >> 3;
    const int bgp = bj & 7;
    int bidx[2];
#pragma unroll
    for (int i = 0; i < 2; ++i) {
        const int k  = brow + 16 * i;
        bidx[i] = ((bNT * 4 + (k >> 3)) * 32 + bgp * 4 + (k & 3)) * 2 + ((k >> 2) & 1); // + 8*t3
    }

    float4 ra[4], rb[2];
    float c[2][4][4];
#pragma unroll
    for (int mt = 0; mt < 2; ++mt)
#pragma unroll
        for (int nt = 0; nt < 4; ++nt)
#pragma unroll
            for (int e = 0; e < 4; ++e) c[mt][nt][e] = 0.f;

    const int nk = K >> 5;

    auto load_chunk = [&](int t) {
        const int kc = t << 5;
#pragma unroll
        for (int i = 0; i < 4; ++i)
            ra[i] = *(const float4*)(A + (size_t)(row0 + arow + 32 * i) * K + kc + aj);
#pragma unroll
        for (int i = 0; i < 2; ++i)
            rb[i] = *(const float4*)(B + (size_t)(kc + brow + 16 * i) * M + col0 + bj);
    };

    auto store_split = [&](int buf) {
        float* Ah = sm + buf * BUF_FLOATS;
        float* Al = Ah + A_HALF;
        float* Bh = Al + A_HALF;
        float* Bl = Bh + B_HALF;
#pragma unroll
        for (int i = 0; i < 4; ++i) {
            const float v[4] = {ra[i].x, ra[i].y, ra[i].z, ra[i].w};
#pragma unroll
            for (int t3 = 0; t3 < 4; ++t3) {
                const float h = tf32r(v[t3]);
                Ah[aidx[i] + 4 * t3] = h;
                Al[aidx[i] + 4 * t3] = tf32r(v[t3] - h);
            }
        }
#pragma unroll
        for (int i = 0; i < 2; ++i) {
            const float v[4] = {rb[i].x, rb[i].y, rb[i].z, rb[i].w};
#pragma unroll
            for (int t3 = 0; t3 < 4; ++t3) {
                const float h = tf32r(v[t3]);
                Bh[bidx[i] + 8 * t3] = h;
                Bl[bidx[i] + 8 * t3] = tf32r(v[t3] - h);
            }
        }
    };

    // prologue
    load_chunk(0);
    store_split(0);
    __syncthreads();

    for (int t = 0; t < nk; ++t) {
        const int cur = t & 1;
        const bool hasNext = (t + 1) < nk;
        if (hasNext) load_chunk(t + 1);       // LDG overlaps compute

        const float* Ahp = sm + cur * BUF_FLOATS;
        const float* Alp = Ahp + A_HALF;
        const float* Bhp = Alp + A_HALF;
        const float* Blp = Bhp + B_HALF;

#pragma unroll
        for (int k8 = 0; k8 < 4; ++k8) {
            // B fragments: one LDS.64 each, conflict-free
            uint32_t bh[4][2], bl[4][2];
#pragma unroll
            for (int nt = 0; nt < 4; ++nt) {
                const int o = ((NTw + nt) * 4 + k8) * 64 + lane * 2;
                float2 h = *(const float2*)(Bhp + o);
                float2 l = *(const float2*)(Blp + o);
                bh[nt][0] = __float_as_uint(h.x); bh[nt][1] = __float_as_uint(h.y);
                bl[nt][0] = __float_as_uint(l.x); bl[nt][1] = __float_as_uint(l.y);
            }
#pragma unroll
            for (int mt = 0; mt < 2; ++mt) {
                const int o = ((Tw + mt) * 4 + k8) * 128 + lane * 4;
                float4 hv = *(const float4*)(Ahp + o);
                float4 lv = *(const float4*)(Alp + o);
                uint32_t ah[4] = {__float_as_uint(hv.x), __float_as_uint(hv.y),
                                  __float_as_uint(hv.z), __float_as_uint(hv.w)};
                uint32_t al[4] = {__float_as_uint(lv.x), __float_as_uint(lv.y),
                                  __float_as_uint(lv.z), __float_as_uint(lv.w)};
#pragma unroll
                for (int nt = 0; nt < 4; ++nt) mma8(c[mt][nt], ah, bh[nt]);
#pragma unroll
                for (int nt = 0; nt < 4; ++nt) mma8(c[mt][nt], ah, bl[nt]);
#pragma unroll
                for (int nt = 0; nt < 4; ++nt) mma8(c[mt][nt], al, bh[nt]);
            }
        }

        if (hasNext) store_split(cur ^ 1);    // write other buffer
        __syncthreads();
    }

    // epilogue: bias + ReLU, float2 stores
#pragma unroll
    for (int mt = 0; mt < 2; ++mt) {
        const int r = row0 + wm + mt * 16 + g;
#pragma unroll
        for (int nt = 0; nt < 4; ++nt) {
            const int cc = col0 + wn + nt * 8 + 2 * tig;
            const float b0 = bias[cc], b1 = bias[cc + 1];
            float2 v0, v1;
            v0.x = fmaxf(c[mt][nt][0] + b0, 0.f);
            v0.y = fmaxf(c[mt][nt][1] + b1, 0.f);
            v1.x = fmaxf(c[mt][nt][2] + b0, 0.f);
            v1.y = fmaxf(c[mt][nt][3] + b1, 0.f);
            *(float2*)(C + (size_t)r * M + cc)       = v0;
            *(float2*)(C + (size_t)(r + 8) * M + cc) = v1;
        }
    }
}

// ---------------------------------------------------------------------------
// Narrow fp32 GEMM: C[N,64] = A[N,K] @ B[K,64] + bias (tiny share of time)
// ---------------------------------------------------------------------------
__global__ __launch_bounds__(256)
void gemm64_bias_k(const float* __restrict__ A, const float* __restrict__ B,
                   const float* __restrict__ bias, float* __restrict__ C, int K)
{
    __shared__ __align__(16) float As[16][128];
    __shared__ __align__(16) float Bsm[16][64];

    const int tid  = threadIdx.x;
    const int row0 = blockIdx.x << 7;
    const int tx   = tid & 15;
    const int ty   = tid >> 4;
    const int aRow = tid >> 2;
    const int aCol = (tid & 3) << 2;
    const int bRow = tid >> 4;
    const int bCol = (tid & 15) << 2;

    float acc[8][4];
#pragma unroll
    for (int i = 0; i < 8; ++i)
#pragma unroll
        for (int j = 0; j < 4; ++j) acc[i][j] = 0.f;

    const int nk = K >> 4;
    for (int t = 0; t < nk; ++t) {
        const int k0 = t << 4;
        float4 a0 = *(const float4*)&A[(size_t)(row0 + aRow)      * K + k0 + aCol];
        float4 a1 = *(const float4*)&A[(size_t)(row0 + aRow + 64) * K + k0 + aCol];
        float4 b0 = *(const float4*)&B[(size_t)(k0 + bRow) * 64 + bCol];
        __syncthreads();
        As[aCol + 0][aRow]      = a0.x; As[aCol + 1][aRow]      = a0.y;
        As[aCol + 2][aRow]      = a0.z; As[aCol + 3][aRow]      = a0.w;
        As[aCol + 0][aRow + 64] = a1.x; As[aCol + 1][aRow + 64] = a1.y;
        As[aCol + 2][aRow + 64] = a1.z; As[aCol + 3][aRow + 64] = a1.w;
        *(float4*)&Bsm[bRow][bCol] = b0;
        __syncthreads();
#pragma unroll
        for (int k = 0; k < 16; ++k) {
            float4 av0 = *(const float4*)&As[k][ty * 8];
            float4 av1 = *(const float4*)&As[k][ty * 8 + 4];
            float4 bv  = *(const float4*)&Bsm[k][tx * 4];
            float a[8] = {av0.x, av0.y, av0.z, av0.w, av1.x, av1.y, av1.z, av1.w};
            float b[4] = {bv.x, bv.y, bv.z, bv.w};
#pragma unroll
            for (int i = 0; i < 8; ++i)
#pragma unroll
                for (int j = 0; j < 4; ++j)
                    acc[i][j] = fmaf(a[i], b[j], acc[i][j]);
        }
    }
#pragma unroll
    for (int i = 0; i < 8; ++i) {
        const int r = row0 + ty * 8 + i;
        float4 v;
        v.x = acc[i][0] + bias[tx * 4 + 0];
        v.y = acc[i][1] + bias[tx * 4 + 1];
        v.z = acc[i][2] + bias[tx * 4 + 2];
        v.w = acc[i][3] + bias[tx * 4 + 3];
        *(float4*)&C[(size_t)r * 64 + tx * 4] = v;
    }
}

// ---------------------------------------------------------------------------
// Router: noisy logits, top-8 (lower index wins ties), masked softmax
// ---------------------------------------------------------------------------
__global__ void router_k(const float* __restrict__ logits,
                         const float* __restrict__ nlogits,
                         const float* __restrict__ noise,
                         float* __restrict__ probs,
                         float* __restrict__ idxOut)
{
    const int t = blockIdx.x * blockDim.x + threadIdx.x;
    if (t >= NTOK) return;

    const float* lg = logits  + (size_t)t * NE;
    const float* nl = nlogits + (size_t)t * NE;
    const float* nz = noise   + (size_t)t * NE;

    float v[NE];
#pragma unroll
    for (int e = 0; e < NE; ++e) {
        float xx = nl[e];
        float sp = fmaxf(xx, 0.f) + log1pf(expf(-fabsf(xx)));
        v[e] = lg[e] + nz[e] * sp;
    }

    int   bi[NKTOP];
    float bv[NKTOP];
#pragma unroll
    for (int j = 0; j < NKTOP; ++j) {
        float m = -INFINITY; int mi = 0;
        for (int e = 0; e < NE; ++e)
            if (v[e] > m) { m = v[e]; mi = e; }
        bv[j] = m; bi[j] = mi; v[mi] = -INFINITY;
    }

    const float mx = bv[0];
    float s = 0.f, ex[NKTOP];
#pragma unroll
    for (int j = 0; j < NKTOP; ++j) { ex[j] = expf(bv[j] - mx); s += ex[j]; }
    const float inv = 1.f / s;

    float o[NE];
#pragma unroll
    for (int e = 0; e < NE; ++e) o[e] = 0.f;
#pragma unroll
    for (int j = 0; j < NKTOP; ++j) o[bi[j]] = ex[j] * inv;

    float* op = probs + (size_t)t * NE;
#pragma unroll
    for (int e = 0; e < NE; e += 4)
        *(float4*)(op + e) = make_float4(o[e], o[e + 1], o[e + 2], o[e + 3]);

    if (idxOut)
#pragma unroll
        for (int j = 0; j < NKTOP; ++j)
            idxOut[(size_t)t * NKTOP + j] = (float)bi[j];
}

// ===========================================================================
extern "C" void kernel_launch(void* const* d_in, const int* in_sizes, int n_in,
                              void* d_out, int out_size)
{
    (void)in_sizes; (void)n_in;

    const float* x     = (const float*)d_in[0];
    const float* noise = (const float*)d_in[1];
    const float* w1    = (const float*)d_in[2];
    const float* b1    = (const float*)d_in[3];
    const float* w2    = (const float*)d_in[4];
    const float* b2    = (const float*)d_in[5];
    const float* wn    = (const float*)d_in[6];
    const float* bn    = (const float*)d_in[7];
    const float* w3    = (const float*)d_in[8];
    const float* b3    = (const float*)d_in[9];
    const float* w4    = (const float*)d_in[10];
    const float* b4    = (const float*)d_in[11];
    const float* wz    = (const float*)d_in[12];
    const float* bz    = (const float*)d_in[13];

    float *h1, *h2, *h4, *lgp, *nlp;
    cudaGetSymbolAddress((void**)&h1,  g_h1);
    cudaGetSymbolAddress((void**)&h2,  g_h2);
    cudaGetSymbolAddress((void**)&h4,  g_h4);
    cudaGetSymbolAddress((void**)&lgp, g_logits);
    cudaGetSymbolAddress((void**)&nlp, g_nlogits);

    cudaFuncSetAttribute(mm_tf32, cudaFuncAttributeMaxDynamicSharedMemorySize, SMEM_BYTES);

    const dim3 blk(256);
    // h1 = relu(x @ w1 + b1)          [32768, 2048]
    mm_tf32<<<dim3(2048 / 64, NTOK / 128), blk, SMEM_BYTES>>>(x,  w1, b1, h1, 1024, 2048);
    // h2 = relu(h1 @ w2 + b2)         [32768, 2048]
    mm_tf32<<<dim3(2048 / 64, NTOK / 128), blk, SMEM_BYTES>>>(h1, w2, b2, h2, 2048, 2048);
    // h1 = relu(h2 @ wn + bn)         [32768, 2048]
    mm_tf32<<<dim3(2048 / 64, NTOK / 128), blk, SMEM_BYTES>>>(h2, wn, bn, h1, 2048, 2048);
    // h4 = relu(h1 @ w3 + b3)         [32768, 1024]
    mm_tf32<<<dim3(1024 / 64, NTOK / 128), blk, SMEM_BYTES>>>(h1, w3, b3, h4, 2048, 1024);

    // expert logits + router
    gemm64_bias_k<<<NTOK / 128, 256>>>(h4, w4, b4, lgp, 1024);
    gemm64_bias_k<<<NTOK / 128, 256>>>(x,  wz, bz, nlp, 1024);

    float* probs  = (float*)d_out;
    float* idxOut = nullptr;
    if (out_size >= NTOK * NE + NTOK * NKTOP)
        idxOut = probs + (size_t)NTOK * NE;
    router_k<<<NTOK / 128, 128>>>(lgp, nlp, noise, probs, idxOut);
}

// round 12
// speedup vs baseline: 2.3048x; 2.3048x over previous
#include <cuda_runtime.h>
#include <math.h>
#include <stdint.h>

#define NTOK 32768
#define NE   64
#define NKTOP 8

// ===========================================================================
// scratch (device globals: allocation-free)
// ===========================================================================
__device__ __align__(16) float g_h1[(size_t)NTOK * 2048];
__device__ __align__(16) float g_h2[(size_t)NTOK * 2048];
__device__ __align__(16) float g_h4[(size_t)NTOK * 1024];
__device__ __align__(16) float g_logits [(size_t)NTOK * NE];
__device__ __align__(16) float g_nlogits[(size_t)NTOK * NE];

// ===========================================================================
// tf32 split-MMA GEMM: C[N,M] = relu(A[N,K] @ W[K,M] + bias)
// - mma.sync.m16n8k8 tf32 (base ISA, plain sm_103 target)
// - fp32 accuracy via 2-way tf32 split, 3 products (hh, hl, lh), err ~2^-22
// - R8: CTA 128x128, warp tile 32x64 (25% fewer smem bytes/MMA than R6's
//   32x32), single-buffer smem 70KB, 2 CTA/SM, R6's proven conflict-free
//   strides and store patterns.
// ===========================================================================
#define A_STRIDE 36            // 32 + 4 pad: A-frag bank == lane (conflict-free)
#define B_STRIDE 136           // 128 + 8 pad: B-frag banks distinct (R5-verified)
#define A_SZ (128 * A_STRIDE)  // floats, one split half
#define B_SZ (32 * B_STRIDE)
#define SMEM_FLOATS (2 * A_SZ + 2 * B_SZ)
#define SMEM_BYTES  (SMEM_FLOATS * 4)   // 71,680 B -> 2 CTA/SM

__device__ __forceinline__ float tf32r(float x) {
    uint32_t h;
    asm("cvt.rna.tf32.f32 %0, %1;" : "=r"(h) : "f"(x));
    return __uint_as_float(h);
}

__device__ __forceinline__ void mma8(float* c, const uint32_t* a, const uint32_t* b) {
    asm volatile(
        "mma.sync.aligned.m16n8k8.row.col.f32.tf32.tf32.f32 "
        "{%0,%1,%2,%3}, {%4,%5,%6,%7}, {%8,%9}, {%0,%1,%2,%3};"
        : "+f"(c[0]), "+f"(c[1]), "+f"(c[2]), "+f"(c[3])
        : "r"(a[0]), "r"(a[1]), "r"(a[2]), "r"(a[3]), "r"(b[0]), "r"(b[1]));
}

__global__ __launch_bounds__(256, 2)
void mm_tf32(const float* __restrict__ A, const float* __restrict__ B,
             const float* __restrict__ bias, float* __restrict__ C,
             int K, int M)
{
    extern __shared__ __align__(16) float sm[];
    float* Ah = sm;
    float* Al = Ah + A_SZ;
    float* Bh = Al + A_SZ;
    float* Bl = Bh + B_SZ;

    const int tid  = threadIdx.x;
    const int lane = tid & 31;
    const int wid  = tid >> 5;
    const int row0 = blockIdx.y << 7;   // 128 rows / CTA
    const int col0 = blockIdx.x << 7;   // 128 cols / CTA
    const int wm   = (wid & 3) << 5;    // warp m-offset: 0/32/64/96
    const int wn   = (wid >> 2) << 6;   // warp n-offset: 0/64
    const int g    = lane >> 2;         // 0..7
    const int tig  = lane & 3;          // 0..3

    // global-load mapping: A tile 128x32 (4 f4/thr), B tile 32x128 (4 f4/thr)
    const int arow = tid >> 3;           // + 32*i
    const int aj   = (tid & 7) << 2;
    const int brow = tid >> 5;           // + 8*i
    const int bj   = (tid & 31) << 2;

    float4 ra[4], rb[4];
    float c[2][8][4];
#pragma unroll
    for (int mt = 0; mt < 2; ++mt)
#pragma unroll
        for (int nt = 0; nt < 8; ++nt)
#pragma unroll
            for (int e = 0; e < 4; ++e) c[mt][nt][e] = 0.f;

    const int nk = K >> 5;

    auto load_chunk = [&](int t) {
        const int kc = t << 5;
#pragma unroll
        for (int i = 0; i < 4; ++i)
            ra[i] = *(const float4*)(A + (size_t)(row0 + arow + 32 * i) * K + kc + aj);
#pragma unroll
        for (int i = 0; i < 4; ++i)
            rb[i] = *(const float4*)(B + (size_t)(kc + brow + 8 * i) * M + col0 + bj);
    };

    auto store_split = [&]() {
#pragma unroll
        for (int i = 0; i < 4; ++i) {
            float4 h, l;
            h.x = tf32r(ra[i].x); l.x = tf32r(ra[i].x - h.x);
            h.y = tf32r(ra[i].y); l.y = tf32r(ra[i].y - h.y);
            h.z = tf32r(ra[i].z); l.z = tf32r(ra[i].z - h.z);
            h.w = tf32r(ra[i].w); l.w = tf32r(ra[i].w - h.w);
            *(float4*)(Ah + (arow + 32 * i) * A_STRIDE + aj) = h;
            *(float4*)(Al + (arow + 32 * i) * A_STRIDE + aj) = l;
        }
#pragma unroll
        for (int i = 0; i < 4; ++i) {
            float4 h, l;
            h.x = tf32r(rb[i].x); l.x = tf32r(rb[i].x - h.x);
            h.y = tf32r(rb[i].y); l.y = tf32r(rb[i].y - h.y);
            h.z = tf32r(rb[i].z); l.z = tf32r(rb[i].z - h.z);
            h.w = tf32r(rb[i].w); l.w = tf32r(rb[i].w - h.w);
            *(float4*)(Bh + (brow + 8 * i) * B_STRIDE + bj) = h;
            *(float4*)(Bl + (brow + 8 * i) * B_STRIDE + bj) = l;
        }
    };

    // prologue
    load_chunk(0);
    store_split();
    __syncthreads();

    for (int t = 0; t < nk; ++t) {
        const bool hasNext = (t + 1) < nk;
        if (hasNext) load_chunk(t + 1);   // LDG overlaps compute below

#pragma unroll
        for (int k8 = 0; k8 < 4; ++k8) {
            // A fragments for both m-tiles (reused across 8 n-tiles)
            uint32_t ah[2][4], al[2][4];
#pragma unroll
            for (int mt = 0; mt < 2; ++mt) {
                const int o = (wm + mt * 16 + g) * A_STRIDE + k8 * 8 + tig;
                ah[mt][0] = __float_as_uint(Ah[o]);
                ah[mt][1] = __float_as_uint(Ah[o + 8 * A_STRIDE]);
                ah[mt][2] = __float_as_uint(Ah[o + 4]);
                ah[mt][3] = __float_as_uint(Ah[o + 8 * A_STRIDE + 4]);
                al[mt][0] = __float_as_uint(Al[o]);
                al[mt][1] = __float_as_uint(Al[o + 8 * A_STRIDE]);
                al[mt][2] = __float_as_uint(Al[o + 4]);
                al[mt][3] = __float_as_uint(Al[o + 8 * A_STRIDE + 4]);
            }
#pragma unroll
            for (int nt = 0; nt < 8; ++nt) {
                const int o = (k8 * 8 + tig) * B_STRIDE + wn + nt * 8 + g;
                uint32_t bh[2], bl[2];
                bh[0] = __float_as_uint(Bh[o]);
                bh[1] = __float_as_uint(Bh[o + 4 * B_STRIDE]);
                bl[0] = __float_as_uint(Bl[o]);
                bl[1] = __float_as_uint(Bl[o + 4 * B_STRIDE]);
                mma8(c[0][nt], ah[0], bh);
                mma8(c[1][nt], ah[1], bh);
                mma8(c[0][nt], ah[0], bl);
                mma8(c[1][nt], ah[1], bl);
                mma8(c[0][nt], al[0], bh);
                mma8(c[1][nt], al[1], bh);
            }
        }

        __syncthreads();                  // all reads of this buffer done
        if (hasNext) {
            store_split();
            __syncthreads();
        }
    }

    // epilogue: bias + ReLU, float2 stores
#pragma unroll
    for (int mt = 0; mt < 2; ++mt) {
        const int r = row0 + wm + mt * 16 + g;
#pragma unroll
        for (int nt = 0; nt < 8; ++nt) {
            const int cc = col0 + wn + nt * 8 + 2 * tig;
            const float b0 = bias[cc], b1 = bias[cc + 1];
            float2 v0, v1;
            v0.x = fmaxf(c[mt][nt][0] + b0, 0.f);
            v0.y = fmaxf(c[mt][nt][1] + b1, 0.f);
            v1.x = fmaxf(c[mt][nt][2] + b0, 0.f);
            v1.y = fmaxf(c[mt][nt][3] + b1, 0.f);
            *(float2*)(C + (size_t)r * M + cc)       = v0;
            *(float2*)(C + (size_t)(r + 8) * M + cc) = v1;
        }
    }
}

// ---------------------------------------------------------------------------
// Narrow fp32 GEMM: C[N,64] = A[N,K] @ B[K,64] + bias (tiny share of time)
// ---------------------------------------------------------------------------
__global__ __launch_bounds__(256)
void gemm64_bias_k(const float* __restrict__ A, const float* __restrict__ B,
                   const float* __restrict__ bias, float* __restrict__ C, int K)
{
    __shared__ __align__(16) float As[16][128];
    __shared__ __align__(16) float Bsm[16][64];

    const int tid  = threadIdx.x;
    const int row0 = blockIdx.x << 7;
    const int tx   = tid & 15;
    const int ty   = tid >> 4;
    const int aRow = tid >> 2;
    const int aCol = (tid & 3) << 2;
    const int bRow = tid >> 4;
    const int bCol = (tid & 15) << 2;

    float acc[8][4];
#pragma unroll
    for (int i = 0; i < 8; ++i)
#pragma unroll
        for (int j = 0; j < 4; ++j) acc[i][j] = 0.f;

    const int nk = K >> 4;
    for (int t = 0; t < nk; ++t) {
        const int k0 = t << 4;
        float4 a0 = *(const float4*)&A[(size_t)(row0 + aRow)      * K + k0 + aCol];
        float4 a1 = *(const float4*)&A[(size_t)(row0 + aRow + 64) * K + k0 + aCol];
        float4 b0 = *(const float4*)&B[(size_t)(k0 + bRow) * 64 + bCol];
        __syncthreads();
        As[aCol + 0][aRow]      = a0.x; As[aCol + 1][aRow]      = a0.y;
        As[aCol + 2][aRow]      = a0.z; As[aCol + 3][aRow]      = a0.w;
        As[aCol + 0][aRow + 64] = a1.x; As[aCol + 1][aRow + 64] = a1.y;
        As[aCol + 2][aRow + 64] = a1.z; As[aCol + 3][aRow + 64] = a1.w;
        *(float4*)&Bsm[bRow][bCol] = b0;
        __syncthreads();
#pragma unroll
        for (int k = 0; k < 16; ++k) {
            float4 av0 = *(const float4*)&As[k][ty * 8];
            float4 av1 = *(const float4*)&As[k][ty * 8 + 4];
            float4 bv  = *(const float4*)&Bsm[k][tx * 4];
            float a[8] = {av0.x, av0.y, av0.z, av0.w, av1.x, av1.y, av1.z, av1.w};
            float b[4] = {bv.x, bv.y, bv.z, bv.w};
#pragma unroll
            for (int i = 0; i < 8; ++i)
#pragma unroll
                for (int j = 0; j < 4; ++j)
                    acc[i][j] = fmaf(a[i], b[j], acc[i][j]);
        }
    }
#pragma unroll
    for (int i = 0; i < 8; ++i) {
        const int r = row0 + ty * 8 + i;
        float4 v;
        v.x = acc[i][0] + bias[tx * 4 + 0];
        v.y = acc[i][1] + bias[tx * 4 + 1];
        v.z = acc[i][2] + bias[tx * 4 + 2];
        v.w = acc[i][3] + bias[tx * 4 + 3];
        *(float4*)&C[(size_t)r * 64 + tx * 4] = v;
    }
}

// ---------------------------------------------------------------------------
// Router: noisy logits, top-8 (lower index wins ties), masked softmax
// ---------------------------------------------------------------------------
__global__ void router_k(const float* __restrict__ logits,
                         const float* __restrict__ nlogits,
                         const float* __restrict__ noise,
                         float* __restrict__ probs,
                         float* __restrict__ idxOut)
{
    const int t = blockIdx.x * blockDim.x + threadIdx.x;
    if (t >= NTOK) return;

    const float* lg = logits  + (size_t)t * NE;
    const float* nl = nlogits + (size_t)t * NE;
    const float* nz = noise   + (size_t)t * NE;

    float v[NE];
#pragma unroll
    for (int e = 0; e < NE; ++e) {
        float xx = nl[e];
        float sp = fmaxf(xx, 0.f) + log1pf(expf(-fabsf(xx)));
        v[e] = lg[e] + nz[e] * sp;
    }

    int   bi[NKTOP];
    float bv[NKTOP];
#pragma unroll
    for (int j = 0; j < NKTOP; ++j) {
        float m = -INFINITY; int mi = 0;
        for (int e = 0; e < NE; ++e)
            if (v[e] > m) { m = v[e]; mi = e; }
        bv[j] = m; bi[j] = mi; v[mi] = -INFINITY;
    }

    const float mx = bv[0];
    float s = 0.f, ex[NKTOP];
#pragma unroll
    for (int j = 0; j < NKTOP; ++j) { ex[j] = expf(bv[j] - mx); s += ex[j]; }
    const float inv = 1.f / s;

    float o[NE];
#pragma unroll
    for (int e = 0; e < NE; ++e) o[e] = 0.f;
#pragma unroll
    for (int j = 0; j < NKTOP; ++j) o[bi[j]] = ex[j] * inv;

    float* op = probs + (size_t)t * NE;
#pragma unroll
    for (int e = 0; e < NE; e += 4)
        *(float4*)(op + e) = make_float4(o[e], o[e + 1], o[e + 2], o[e + 3]);

    if (idxOut)
#pragma unroll
        for (int j = 0; j < NKTOP; ++j)
            idxOut[(size_t)t * NKTOP + j] = (float)bi[j];
}

// ===========================================================================
extern "C" void kernel_launch(void* const* d_in, const int* in_sizes, int n_in,
                              void* d_out, int out_size)
{
    (void)in_sizes; (void)n_in;

    const float* x     = (const float*)d_in[0];
    const float* noise = (const float*)d_in[1];
    const float* w1    = (const float*)d_in[2];
    const float* b1    = (const float*)d_in[3];
    const float* w2    = (const float*)d_in[4];
    const float* b2    = (const float*)d_in[5];
    const float* wn    = (const float*)d_in[6];
    const float* bn    = (const float*)d_in[7];
    const float* w3    = (const float*)d_in[8];
    const float* b3    = (const float*)d_in[9];
    const float* w4    = (const float*)d_in[10];
    const float* b4    = (const float*)d_in[11];
    const float* wz    = (const float*)d_in[12];
    const float* bz    = (const float*)d_in[13];

    float *h1, *h2, *h4, *lgp, *nlp;
    cudaGetSymbolAddress((void**)&h1,  g_h1);
    cudaGetSymbolAddress((void**)&h2,  g_h2);
    cudaGetSymbolAddress((void**)&h4,  g_h4);
    cudaGetSymbolAddress((void**)&lgp, g_logits);
    cudaGetSymbolAddress((void**)&nlp, g_nlogits);

    cudaFuncSetAttribute(mm_tf32, cudaFuncAttributeMaxDynamicSharedMemorySize, SMEM_BYTES);

    const dim3 blk(256);
    // h1 = relu(x @ w1 + b1)          [32768, 2048]
    mm_tf32<<<dim3(2048 / 128, NTOK / 128), blk, SMEM_BYTES>>>(x,  w1, b1, h1, 1024, 2048);
    // h2 = relu(h1 @ w2 + b2)         [32768, 2048]
    mm_tf32<<<dim3(2048 / 128, NTOK / 128), blk, SMEM_BYTES>>>(h1, w2, b2, h2, 2048, 2048);
    // h1 = relu(h2 @ wn + bn)         [32768, 2048]
    mm_tf32<<<dim3(2048 / 128, NTOK / 128), blk, SMEM_BYTES>>>(h2, wn, bn, h1, 2048, 2048);
    // h4 = relu(h1 @ w3 + b3)         [32768, 1024]
    mm_tf32<<<dim3(1024 / 128, NTOK / 128), blk, SMEM_BYTES>>>(h1, w3, b3, h4, 2048, 1024);

    // expert logits + router
    gemm64_bias_k<<<NTOK / 128, 256>>>(h4, w4, b4, lgp, 1024);
    gemm64_bias_k<<<NTOK / 128, 256>>>(x,  wz, bz, nlp, 1024);

    float* probs  = (float*)d_out;
    float* idxOut = nullptr;
    if (out_size >= NTOK * NE + NTOK * NKTOP)
        idxOut = probs + (size_t)NTOK * NE;
    router_k<<<NTOK / 128, 128>>>(lgp, nlp, noise, probs, idxOut);
}